// round 2
// baseline (speedup 1.0000x reference)
#include <cuda_runtime.h>
#include <cstdint>

// Problem constants (fixed by the dataset: 16 clips of 10 s @ 48 kHz)
#define N_SAMP  480000
#define NP1     480001          // envelope length per row
#define WIN     240             // 5 ms box filter
#define EPSF    1e-6f

// Tiling
#define T_OUT   2048            // envelope outputs per block
#define NTHR    256
#define EPT     9               // scan elements per thread (256*9 = 2304 >= L_D)
#define L_D     2287            // valid d elements needed per tile: T_OUT + WIN - 1
#define XS_SZ   2320            // staged x values (L_D+1 = 2288, padded)
#define P_SZ    2320            // prefix sums (indices 0..2304 written, 0..2287 read)

// Scratch (no allocations allowed)
__device__ int    g_rowmax_i[64];   // per-row envelope max of y_true, float bits
__device__ double g_sum;            // global loss accumulator

struct SM {
    float xs[XS_SZ];
    float P[P_SZ];
    float wsum[8];
    float wbase[8];
    float red[8];
};

// Computes env[256*e + t] for e in [0,8) for the tile starting at output j0.
// env[jj] = (1/240) * sum_{i=j0+jj-120}^{j0+jj+119} d[i], d[i]=|x[i]-x[i-1]| (d[0]=0, OOB=0)
__device__ __forceinline__ void compute_env(const float* __restrict__ xr, int j0,
                                            SM* sm, float env[8])
{
    const int t = threadIdx.x;
    // Stage x[j0-121 .. j0+T_OUT+118] into shared (coalesced), zero OOB/pad.
    for (int k = t; k < XS_SZ; k += NTHR) {
        int i = j0 - 121 + k;
        float v = 0.f;
        if (k <= L_D && i >= 0 && i < N_SAMP) v = xr[i];
        sm->xs[k] = v;
    }
    __syncthreads();

    // Per-thread serial scan over 9 consecutive d values (stride-9 smem reads:
    // gcd(9,32)=1 -> conflict free across a warp).
    float run[EPT];
    float s = 0.f;
    const int m0 = EPT * t;
    #pragma unroll
    for (int e = 0; e < EPT; e++) {
        int m  = m0 + e;
        int id = j0 - 120 + m;          // global d index
        float dv = 0.f;
        if (m < L_D && id >= 1 && id < N_SAMP)
            dv = fabsf(sm->xs[m + 1] - sm->xs[m]);
        s += dv;
        run[e] = s;                     // thread-local inclusive
    }

    // Warp inclusive scan of thread totals
    const int lane = t & 31, wid = t >> 5;
    float v = s;
    #pragma unroll
    for (int off = 1; off < 32; off <<= 1) {
        float u = __shfl_up_sync(0xffffffffu, v, off);
        if (lane >= off) v += u;
    }
    if (lane == 31) sm->wsum[wid] = v;
    __syncthreads();
    if (t == 0) {
        float acc = 0.f;
        #pragma unroll
        for (int w = 0; w < 8; w++) { sm->wbase[w] = acc; acc += sm->wsum[w]; }
    }
    __syncthreads();

    const float base = sm->wbase[wid] + (v - s);  // exclusive prefix for this thread
    #pragma unroll
    for (int e = 0; e < EPT; e++) sm->P[m0 + e + 1] = base + run[e];
    if (t == 0) sm->P[0] = 0.f;
    __syncthreads();

    const float inv = 1.f / (float)WIN;
    #pragma unroll
    for (int e = 0; e < 8; e++) {
        int jj = (e << 8) + t;                        // 0..2047
        env[e] = (sm->P[jj + WIN] - sm->P[jj]) * inv; // max idx 2287 < P_SZ
    }
    __syncthreads();   // allow shared reuse by a second compute_env call
}

__global__ void k_init()
{
    int t = threadIdx.x;
    if (t < 64) g_rowmax_i[t] = 0;
    if (t == 0) g_sum = 0.0;
}

__global__ void k_envmax(const float* __restrict__ y_true)
{
    __shared__ SM sm;
    const int row = blockIdx.y;
    const int j0  = blockIdx.x * T_OUT;
    const float* xr = y_true + (size_t)row * N_SAMP;

    float env[8];
    compute_env(xr, j0, &sm, env);

    float mx = 0.f;
    #pragma unroll
    for (int e = 0; e < 8; e++) {
        int j = j0 + (e << 8) + threadIdx.x;
        if (j < NP1) mx = fmaxf(mx, env[e]);
    }
    const int lane = threadIdx.x & 31, wid = threadIdx.x >> 5;
    #pragma unroll
    for (int off = 16; off > 0; off >>= 1)
        mx = fmaxf(mx, __shfl_down_sync(0xffffffffu, mx, off));
    if (lane == 0) sm.red[wid] = mx;
    __syncthreads();
    if (threadIdx.x == 0) {
        float m = sm.red[0];
        #pragma unroll
        for (int w = 1; w < 8; w++) m = fmaxf(m, sm.red[w]);
        atomicMax(&g_rowmax_i[row], __float_as_int(m));  // valid: all values >= 0
    }
}

__global__ void k_loss(const float* __restrict__ y_pred,
                       const float* __restrict__ y_true)
{
    __shared__ SM sm;
    const int row = blockIdx.y;
    const int j0  = blockIdx.x * T_OUT;
    const float* xp = y_pred + (size_t)row * N_SAMP;
    const float* xt = y_true + (size_t)row * N_SAMP;

    float Ep[8], Et[8];
    compute_env(xp, j0, &sm, Ep);
    compute_env(xt, j0, &sm, Et);

    const float rmax = __int_as_float(g_rowmax_i[row]);
    const float winv = 1.f / (rmax + EPSF);

    float lsum = 0.f;
    #pragma unroll
    for (int e = 0; e < 8; e++) {
        int j = j0 + (e << 8) + threadIdx.x;
        if (j < NP1) {
            float df = fabsf(__logf(Ep[e] + EPSF) - __logf(Et[e] + EPSF));
            float w  = Et[e] * winv;
            lsum += df * (0.2f + 0.8f * w);
        }
    }
    const int lane = threadIdx.x & 31, wid = threadIdx.x >> 5;
    #pragma unroll
    for (int off = 16; off > 0; off >>= 1)
        lsum += __shfl_down_sync(0xffffffffu, lsum, off);
    if (lane == 0) sm.red[wid] = lsum;
    __syncthreads();
    if (threadIdx.x == 0) {
        float bs = sm.red[0];
        #pragma unroll
        for (int w = 1; w < 8; w++) bs += sm.red[w];
        atomicAdd(&g_sum, (double)bs);
    }
}

__global__ void k_final(float* __restrict__ out, double invcnt)
{
    out[0] = (float)(g_sum * invcnt);
}

extern "C" void kernel_launch(void* const* d_in, const int* in_sizes, int n_in,
                              void* d_out, int out_size)
{
    const float* y_pred = (const float*)d_in[0];
    const float* y_true = (const float*)d_in[1];
    float* out = (float*)d_out;

    const int B = in_sizes[0] / N_SAMP;
    const int tiles = (NP1 + T_OUT - 1) / T_OUT;   // 235

    k_init<<<1, 64>>>();
    k_envmax<<<dim3(tiles, B), NTHR>>>(y_true);
    k_loss<<<dim3(tiles, B), NTHR>>>(y_pred, y_true);
    k_final<<<1, 1>>>(out, 1.0 / ((double)B * (double)NP1));
}

// round 3
// speedup vs baseline: 1.2812x; 1.2812x over previous
#include <cuda_runtime.h>
#include <cstdint>

// Problem constants (16 clips of 10 s @ 48 kHz)
#define N_SAMP  480000
#define NP1     480001          // envelope length per row
#define WIN     240             // 5 ms box filter
#define EPSF    1e-6f

// Tiling
#define T_OUT   2048            // envelope outputs per block
#define NTHR    256
#define EPT     9               // scan elems/thread (256*9 = 2304 >= L_D)
#define L_D     2287            // d elements needed per tile: T_OUT + WIN - 1
#define XS_SZ   2320            // staged x values (L_D+1 = 2288, padded)
#define P_SZ    2320

#define MAXB    16

// Scratch (zero-initialized at module load; reset by last block each run)
struct RowAcc { double s1, s2; int m; int pad[3]; };   // 32 B, rows on distinct banks
__device__ RowAcc      g_acc[MAXB];
__device__ unsigned int g_count;

struct SM2 {
    float xsP[XS_SZ], xsT[XS_SZ];
    float PP[P_SZ],  PT[P_SZ];
    float wsP[8], wsT[8], wbP[8], wbT[8];
    float r1[8], r2[8], r3[8];
};

__global__ __launch_bounds__(NTHR)
void k_fused(const float* __restrict__ y_pred, const float* __restrict__ y_true,
             float* __restrict__ out, int B, double invcnt)
{
    __shared__ SM2 sm;
    const int t   = threadIdx.x;
    const int row = blockIdx.y;
    const int j0  = blockIdx.x * T_OUT;
    const float* xp = y_pred + (size_t)row * N_SAMP;
    const float* xt = y_true + (size_t)row * N_SAMP;

    // ---- Stage x[j0-121 .. j0+T_OUT+118] for both signals (coalesced) ----
    for (int k = t; k < XS_SZ; k += NTHR) {
        int i = j0 - 121 + k;
        bool valid = (k <= L_D && i >= 0 && i < N_SAMP);
        sm.xsP[k] = valid ? __ldg(xp + i) : 0.f;
        sm.xsT[k] = valid ? __ldg(xt + i) : 0.f;
    }
    __syncthreads();

    // ---- Per-thread serial scan over 9 consecutive d values, both signals ----
    // stride-9 smem reads: gcd(9,32)=1 -> conflict free across a warp.
    float runP[EPT], runT[EPT];
    float sP = 0.f, sT = 0.f;
    const int m0 = EPT * t;
    #pragma unroll
    for (int e = 0; e < EPT; e++) {
        int m  = m0 + e;
        int id = j0 - 120 + m;            // global d index
        float dP = 0.f, dT = 0.f;
        if (m < L_D && id >= 1 && id < N_SAMP) {
            dP = fabsf(sm.xsP[m + 1] - sm.xsP[m]);
            dT = fabsf(sm.xsT[m + 1] - sm.xsT[m]);
        }
        sP += dP; runP[e] = sP;
        sT += dT; runT[e] = sT;
    }

    // ---- Warp inclusive scans of thread totals (two independent chains) ----
    const int lane = t & 31, wid = t >> 5;
    float vP = sP, vT = sT;
    #pragma unroll
    for (int off = 1; off < 32; off <<= 1) {
        float uP = __shfl_up_sync(0xffffffffu, vP, off);
        float uT = __shfl_up_sync(0xffffffffu, vT, off);
        if (lane >= off) { vP += uP; vT += uT; }
    }
    if (lane == 31) { sm.wsP[wid] = vP; sm.wsT[wid] = vT; }
    __syncthreads();
    if (t == 0) {
        float a = 0.f;
        #pragma unroll
        for (int w = 0; w < 8; w++) { sm.wbP[w] = a; a += sm.wsP[w]; }
    }
    if (t == 1) {
        float a = 0.f;
        #pragma unroll
        for (int w = 0; w < 8; w++) { sm.wbT[w] = a; a += sm.wsT[w]; }
    }
    __syncthreads();

    const float baseP = sm.wbP[wid] + (vP - sP);
    const float baseT = sm.wbT[wid] + (vT - sT);
    #pragma unroll
    for (int e = 0; e < EPT; e++) {
        sm.PP[m0 + e + 1] = baseP + runP[e];
        sm.PT[m0 + e + 1] = baseT + runT[e];
    }
    if (t == 0) { sm.PP[0] = 0.f; sm.PT[0] = 0.f; }
    __syncthreads();

    // ---- Envelope diff + partial reductions (S1, S2, M) ----
    const float inv = 1.f / (float)WIN;
    float s1 = 0.f, s2 = 0.f, mx = 0.f;
    #pragma unroll
    for (int e = 0; e < 8; e++) {
        int jj = (e << 8) + t;
        int j  = j0 + jj;
        if (j < NP1) {
            float Ep = (sm.PP[jj + WIN] - sm.PP[jj]) * inv;
            float Et = (sm.PT[jj + WIN] - sm.PT[jj]) * inv;
            float df = fabsf(__logf(Ep + EPSF) - __logf(Et + EPSF));
            s1 += df;
            s2 += df * Et;
            mx  = fmaxf(mx, Et);
        }
    }
    #pragma unroll
    for (int off = 16; off > 0; off >>= 1) {
        s1 += __shfl_down_sync(0xffffffffu, s1, off);
        s2 += __shfl_down_sync(0xffffffffu, s2, off);
        mx  = fmaxf(mx, __shfl_down_sync(0xffffffffu, mx, off));
    }
    if (lane == 0) { sm.r1[wid] = s1; sm.r2[wid] = s2; sm.r3[wid] = mx; }
    __syncthreads();

    if (t == 0) {
        float a1 = 0.f, a2 = 0.f, am = 0.f;
        #pragma unroll
        for (int w = 0; w < 8; w++) {
            a1 += sm.r1[w]; a2 += sm.r2[w]; am = fmaxf(am, sm.r3[w]);
        }
        atomicAdd(&g_acc[row].s1, (double)a1);
        atomicAdd(&g_acc[row].s2, (double)a2);
        atomicMax(&g_acc[row].m, __float_as_int(am));   // valid: env >= 0
        __threadfence();

        unsigned int total = gridDim.x * gridDim.y;
        unsigned int old = atomicAdd(&g_count, 1u);
        if (old == total - 1u) {
            // Last block: finalize, write output, reset scratch for next replay.
            __threadfence();
            double tot = 0.0;
            for (int r = 0; r < B; r++) {
                volatile double* p1 = &g_acc[r].s1;
                volatile double* p2 = &g_acc[r].s2;
                volatile int*    pm = &g_acc[r].m;
                double S1 = *p1;
                double S2 = *p2;
                float  M  = __int_as_float(*pm);
                tot += 0.2 * S1 + 0.8 * S2 / ((double)M + (double)EPSF);
                g_acc[r].s1 = 0.0; g_acc[r].s2 = 0.0; g_acc[r].m = 0;
            }
            out[0] = (float)(tot * invcnt);
            g_count = 0u;
            __threadfence();
        }
    }
}

extern "C" void kernel_launch(void* const* d_in, const int* in_sizes, int n_in,
                              void* d_out, int out_size)
{
    const float* y_pred = (const float*)d_in[0];
    const float* y_true = (const float*)d_in[1];
    float* out = (float*)d_out;

    const int B     = in_sizes[0] / N_SAMP;          // 16
    const int tiles = (NP1 + T_OUT - 1) / T_OUT;     // 235

    k_fused<<<dim3(tiles, B), NTHR>>>(y_pred, y_true, out, B,
                                      1.0 / ((double)B * (double)NP1));
}

// round 4
// speedup vs baseline: 1.5513x; 1.2108x over previous
#include <cuda_runtime.h>
#include <cstdint>

// Problem constants (16 clips of 10 s @ 48 kHz)
#define N_SAMP  480000
#define NP1     480001          // envelope length per row
#define WIN     240             // 5 ms box filter
#define EPSF    1e-6f

// Tiling
#define T_OUT   2048            // envelope outputs per block
#define NTHR    256
#define EPT     9               // scan elems/thread (256*9 = 2304 >= L_D)
#define L_D     2287            // d elements per tile: T_OUT + WIN - 1
#define XS_SZ   2320            // staged floats (covers reads up to idx 2307)
#define XS4     580             // XS_SZ / 4
#define OFFX    124             // stage window start j0-124 (16B aligned)

#define MAXB    16

// Scratch (zero-initialized at load; reset by last block each run)
struct RowAcc { double s1, s2; int m; int pad[3]; };
__device__ RowAcc       g_acc[MAXB];
__device__ unsigned int g_count;

struct __align__(16) SMF {
    float bP[XS_SZ];            // staged y_pred, later overwritten with prefix P
    float bT[XS_SZ];            // staged y_true, later overwritten with prefix P
    float wsP[8], wsT[8];
    float r1[8], r2[8], r3[8];
};

// d_m = |x[id]-x[id-1]|, id = j0-120+m = (j0-OFFX) + m + 4  ->  uses bX[m+3], bX[m+4]
template<bool INTERIOR>
__device__ __forceinline__ void body(SMF& sm,
                                     const float* __restrict__ xp,
                                     const float* __restrict__ xt,
                                     int j0, float& s1, float& s2, float& mx)
{
    const int t  = threadIdx.x;
    const int w0 = j0 - OFFX;

    // ---- Stage both signals ----
    if (INTERIOR) {
        // w0 is a multiple of 4 and in-bounds for the whole window.
        const float4* p4 = reinterpret_cast<const float4*>(xp + w0);
        const float4* q4 = reinterpret_cast<const float4*>(xt + w0);
        float4* bP4 = reinterpret_cast<float4*>(sm.bP);
        float4* bT4 = reinterpret_cast<float4*>(sm.bT);
        bP4[t]       = p4[t];
        bT4[t]       = q4[t];
        bP4[t + 256] = p4[t + 256];
        bT4[t + 256] = q4[t + 256];
        if (t < XS4 - 512) {
            bP4[t + 512] = p4[t + 512];
            bT4[t + 512] = q4[t + 512];
        }
    } else {
        for (int k = t; k < XS_SZ; k += NTHR) {
            int i = w0 + k;
            bool v = (i >= 0 && i < N_SAMP);
            sm.bP[k] = v ? xp[i] : 0.f;
            sm.bT[k] = v ? xt[i] : 0.f;
        }
    }
    __syncthreads();

    // ---- Per-thread diffs + running sums (regs); stride-9 LDS is conflict-free ----
    const int m0 = EPT * t;
    float rP[EPT], rT[EPT];
    float sP = 0.f, sT = 0.f;
    {
        float a[EPT + 1];
        #pragma unroll
        for (int e = 0; e <= EPT; e++) a[e] = sm.bP[m0 + 3 + e];
        #pragma unroll
        for (int e = 0; e < EPT; e++) {
            bool ok = (m0 + e < L_D);
            if (!INTERIOR) {
                int id = j0 - 120 + m0 + e;
                ok = ok && (id >= 1) && (id < N_SAMP);
            }
            float dv = ok ? fabsf(a[e + 1] - a[e]) : 0.f;
            sP += dv; rP[e] = sP;
        }
    }
    {
        float a[EPT + 1];
        #pragma unroll
        for (int e = 0; e <= EPT; e++) a[e] = sm.bT[m0 + 3 + e];
        #pragma unroll
        for (int e = 0; e < EPT; e++) {
            bool ok = (m0 + e < L_D);
            if (!INTERIOR) {
                int id = j0 - 120 + m0 + e;
                ok = ok && (id >= 1) && (id < N_SAMP);
            }
            float dv = ok ? fabsf(a[e + 1] - a[e]) : 0.f;
            sT += dv; rT[e] = sT;
        }
    }

    // ---- Warp inclusive scans of thread totals (two independent chains) ----
    const int lane = t & 31, wid = t >> 5;
    float vP = sP, vT = sT;
    #pragma unroll
    for (int off = 1; off < 32; off <<= 1) {
        float uP = __shfl_up_sync(0xffffffffu, vP, off);
        float uT = __shfl_up_sync(0xffffffffu, vT, off);
        if (lane >= off) { vP += uP; vT += uT; }
    }
    if (lane == 31) { sm.wsP[wid] = vP; sm.wsT[wid] = vT; }
    __syncthreads();   // also separates all bP/bT reg-loads from the P overwrite

    // Per-thread exclusive base: sum warp totals below own warp (broadcast LDS)
    float baseP = vP - sP, baseT = vT - sT;
    #pragma unroll
    for (int w = 0; w < 7; w++) {
        if (w < wid) { baseP += sm.wsP[w]; baseT += sm.wsT[w]; }
    }

    // ---- Write prefix P in place over the staged x ----
    #pragma unroll
    for (int e = 0; e < EPT; e++) {
        sm.bP[m0 + e + 1] = baseP + rP[e];
        sm.bT[m0 + e + 1] = baseT + rT[e];
    }
    if (t == 0) { sm.bP[0] = 0.f; sm.bT[0] = 0.f; }
    __syncthreads();

    // ---- Envelopes + partial sums ----
    const float inv = 1.f / (float)WIN;
    #pragma unroll
    for (int e = 0; e < 8; e++) {
        int jj = (e << 8) + t;
        if (INTERIOR || (j0 + jj < NP1)) {
            float Ep = (sm.bP[jj + WIN] - sm.bP[jj]) * inv;
            float Et = (sm.bT[jj + WIN] - sm.bT[jj]) * inv;
            float df = fabsf(__logf(Ep + EPSF) - __logf(Et + EPSF));
            s1 += df; s2 += df * Et; mx = fmaxf(mx, Et);
        }
    }
}

__global__ __launch_bounds__(NTHR)
void k_fused(const float* __restrict__ y_pred, const float* __restrict__ y_true,
             float* __restrict__ out, int B, double invcnt)
{
    __shared__ SMF sm;
    const int row = blockIdx.y;
    const int j0  = blockIdx.x * T_OUT;
    const float* xp = y_pred + (size_t)row * N_SAMP;
    const float* xt = y_true + (size_t)row * N_SAMP;

    float s1 = 0.f, s2 = 0.f, mx = 0.f;
    if (blockIdx.x >= 1 && blockIdx.x < gridDim.x - 1)
        body<true >(sm, xp, xt, j0, s1, s2, mx);
    else
        body<false>(sm, xp, xt, j0, s1, s2, mx);

    // ---- Block reduction of (S1, S2, M) ----
    const int lane = threadIdx.x & 31, wid = threadIdx.x >> 5;
    #pragma unroll
    for (int off = 16; off > 0; off >>= 1) {
        s1 += __shfl_down_sync(0xffffffffu, s1, off);
        s2 += __shfl_down_sync(0xffffffffu, s2, off);
        mx  = fmaxf(mx, __shfl_down_sync(0xffffffffu, mx, off));
    }
    if (lane == 0) { sm.r1[wid] = s1; sm.r2[wid] = s2; sm.r3[wid] = mx; }
    __syncthreads();

    if (threadIdx.x == 0) {
        float a1 = 0.f, a2 = 0.f, am = 0.f;
        #pragma unroll
        for (int w = 0; w < 8; w++) {
            a1 += sm.r1[w]; a2 += sm.r2[w]; am = fmaxf(am, sm.r3[w]);
        }
        atomicAdd(&g_acc[row].s1, (double)a1);
        atomicAdd(&g_acc[row].s2, (double)a2);
        atomicMax(&g_acc[row].m, __float_as_int(am));   // valid: env >= 0
        __threadfence();

        unsigned int total = gridDim.x * gridDim.y;
        unsigned int old = atomicAdd(&g_count, 1u);
        if (old == total - 1u) {
            // Last block: finalize, write output, reset scratch for next replay.
            __threadfence();
            double tot = 0.0;
            for (int r = 0; r < B; r++) {
                volatile double* p1 = &g_acc[r].s1;
                volatile double* p2 = &g_acc[r].s2;
                volatile int*    pm = &g_acc[r].m;
                double S1 = *p1;
                double S2 = *p2;
                float  M  = __int_as_float(*pm);
                tot += 0.2 * S1 + 0.8 * S2 / ((double)M + (double)EPSF);
                g_acc[r].s1 = 0.0; g_acc[r].s2 = 0.0; g_acc[r].m = 0;
            }
            out[0] = (float)(tot * invcnt);
            g_count = 0u;
            __threadfence();
        }
    }
}

extern "C" void kernel_launch(void* const* d_in, const int* in_sizes, int n_in,
                              void* d_out, int out_size)
{
    const float* y_pred = (const float*)d_in[0];
    const float* y_true = (const float*)d_in[1];
    float* out = (float*)d_out;

    const int B     = in_sizes[0] / N_SAMP;          // 16
    const int tiles = (NP1 + T_OUT - 1) / T_OUT;     // 235

    k_fused<<<dim3(tiles, B), NTHR>>>(y_pred, y_true, out, B,
                                      1.0 / ((double)B * (double)NP1));
}